// round 2
// baseline (speedup 1.0000x reference)
#include <cuda_runtime.h>
#include <cstdint>
#include <cstddef>

#define D   64
#define H   4
#define NEG 0.2f
#define BN_EPS 1e-5f

#define NMAX 50000
#define EMAX 800000

// ---------------- scratch (static device globals; no allocation) ----------------
__device__ float  g_u[(size_t)NMAX * D];        // [N,64] post-PReLU features
__device__ float  g_z[(size_t)NMAX * 256];      // [N,H,64] aggregated (head-scaled)
__device__ float  g_asrc[NMAX * H];
__device__ float  g_adst[NMAX * H];
__device__ float  g_cs[H * D];                  // W_gat_h^T att_src_h
__device__ float  g_cd[H * D];                  // W_gat_h^T att_dst_h
__device__ int    g_cnt[NMAX];
__device__ int    g_rowptr[NMAX + 1];
__device__ int    g_cursor[NMAX];
__device__ int    g_csrc[EMAX];
__device__ int    g_bsum[256];
__device__ double g_sums[128];                  // [0:64) sum, [64:128) sumsq
__device__ float  g_bnsc[64], g_bnsh[64];

// ============================================================================
// K0: c_src/c_dst projection vectors + zero sums/counters prep
// ============================================================================
__global__ void k_prep(const float* __restrict__ Wgat,
                       const float* __restrict__ attS,
                       const float* __restrict__ attD) {
    int tid = threadIdx.x;              // 256
    if (tid < 128) g_sums[tid] = 0.0;
    int h = tid >> 6, k = tid & 63;
    float s = 0.f, d2 = 0.f;
    #pragma unroll 8
    for (int dd = 0; dd < 64; dd++) {
        float wv = Wgat[(h * 64 + dd) * 64 + k];
        s  += attS[h * 64 + dd] * wv;
        d2 += attD[h * 64 + dd] * wv;
    }
    g_cs[tid] = s;
    g_cd[tid] = d2;
}

// ============================================================================
// K1: u = PReLU(x W_lin^T + b); a_src = u.c_s; a_dst = u.c_d
// Block: 64 rows, 256 threads.
// ============================================================================
#define K1_SMEM ((3*64*72 + 2*4*68) * 4)

__global__ __launch_bounds__(256) void k_linear(
    const float* __restrict__ x, const float* __restrict__ Wlin,
    const float* __restrict__ blin, const float* __restrict__ pw, int nrows)
{
    extern __shared__ float sm[];
    float* sX = sm;                  // [64][72]  xT
    float* sU = sm + 64 * 72;        // [64][72]  uT
    float* sW = sm + 2 * 64 * 72;    // [64][72]  Wlin^T
    float* sC = sm + 3 * 64 * 72;            // [4][68]
    float* sC2 = sC + 4 * 68;                // [4][68]
    const int tid  = threadIdx.x;
    const int row0 = blockIdx.x * 64;

    if (tid < 256) {
        int h = tid >> 6, k = tid & 63;
        sC [h * 68 + k] = g_cs[tid];
        sC2[h * 68 + k] = g_cd[tid];
    }
    for (int i = tid; i < 64 * 64; i += 256) {
        int r = i >> 6, k = i & 63;
        int gr = row0 + r;
        sX[k * 72 + r] = (gr < nrows) ? x[(size_t)gr * D + k] : 0.f;
    }
    for (int i = tid; i < 64 * 64; i += 256) {
        int j = i >> 6, k = i & 63;
        sW[k * 72 + j] = Wlin[i];
    }
    __syncthreads();

    {
        const int rg = (tid >> 4) << 2;
        const int cg = (tid & 15) << 2;
        float acc[4][4];
        #pragma unroll
        for (int a = 0; a < 4; a++)
            #pragma unroll
            for (int b = 0; b < 4; b++) acc[a][b] = 0.f;
        #pragma unroll 8
        for (int k = 0; k < 64; k++) {
            float4 a4 = *(const float4*)(sX + k * 72 + rg);
            float4 b4 = *(const float4*)(sW + k * 72 + cg);
            float av[4] = {a4.x, a4.y, a4.z, a4.w};
            float bv[4] = {b4.x, b4.y, b4.z, b4.w};
            #pragma unroll
            for (int ri = 0; ri < 4; ri++)
                #pragma unroll
                for (int cj = 0; cj < 4; cj++) acc[ri][cj] += av[ri] * bv[cj];
        }
        float4 bb = *(const float4*)(blin + cg);
        float4 pp = *(const float4*)(pw + cg);
        float bvb[4] = {bb.x, bb.y, bb.z, bb.w};
        float pvb[4] = {pp.x, pp.y, pp.z, pp.w};
        #pragma unroll
        for (int ri = 0; ri < 4; ri++) {
            float v4[4];
            #pragma unroll
            for (int cj = 0; cj < 4; cj++) {
                float v = acc[ri][cj] + bvb[cj];
                v = (v >= 0.f) ? v : pvb[cj] * v;
                sU[(cg + cj) * 72 + rg + ri] = v;
                v4[cj] = v;
            }
            int gr = row0 + rg + ri;
            if (gr < nrows)
                *(float4*)(g_u + (size_t)gr * D + cg) =
                    make_float4(v4[0], v4[1], v4[2], v4[3]);
        }
    }
    __syncthreads();

    // attention dot products: thread = (row r, head h)
    {
        const int r = tid >> 2, h = tid & 3;
        float sa = 0.f, da = 0.f;
        #pragma unroll 8
        for (int k = 0; k < 64; k++) {
            float uv = sU[k * 72 + r];
            sa += uv * sC [h * 68 + k];
            da += uv * sC2[h * 68 + k];
        }
        int gr = row0 + r;
        if (gr < nrows) {
            g_asrc[gr * 4 + h] = sa;
            g_adst[gr * 4 + h] = da;
        }
    }
}

// ============================================================================
// CSR build
// ============================================================================
__global__ void k_zero_cnt(int n) {
    int i = blockIdx.x * blockDim.x + threadIdx.x;
    if (i < n) g_cnt[i] = 0;
}

__global__ void k_hist(const int* __restrict__ dst, int e) {
    for (int i = blockIdx.x * blockDim.x + threadIdx.x; i < e;
         i += gridDim.x * blockDim.x)
        atomicAdd(&g_cnt[dst[i]], 1);
}

__global__ void k_scanA(int n) {
    __shared__ int sh[512];
    int i = blockIdx.x * 512 + threadIdx.x;
    int v = (i < n) ? g_cnt[i] : 0;
    sh[threadIdx.x] = v;
    __syncthreads();
    #pragma unroll
    for (int off = 1; off < 512; off <<= 1) {
        int t = (threadIdx.x >= off) ? sh[threadIdx.x - off] : 0;
        __syncthreads();
        sh[threadIdx.x] += t;
        __syncthreads();
    }
    if (i < n) g_rowptr[i] = sh[threadIdx.x] - v;   // exclusive within block
    if (threadIdx.x == 511) g_bsum[blockIdx.x] = sh[511];
}

__global__ void k_scanB(int nch) {       // 256-thread block scan (exclusive)
    __shared__ int sh[256];
    int v = (threadIdx.x < nch) ? g_bsum[threadIdx.x] : 0;
    sh[threadIdx.x] = v;
    __syncthreads();
    #pragma unroll
    for (int off = 1; off < 256; off <<= 1) {
        int t = (threadIdx.x >= off) ? sh[threadIdx.x - off] : 0;
        __syncthreads();
        sh[threadIdx.x] += t;
        __syncthreads();
    }
    if (threadIdx.x < nch) g_bsum[threadIdx.x] = sh[threadIdx.x] - v;
}

__global__ void k_scanC(int n, int e) {
    int i = blockIdx.x * blockDim.x + threadIdx.x;
    if (i < n) {
        int v = g_rowptr[i] + g_bsum[i >> 9];
        g_rowptr[i] = v;
        g_cursor[i] = v;
    }
    if (i == 0) g_rowptr[n] = e;
}

__global__ void k_scatter(const int* __restrict__ src, const int* __restrict__ dst, int e) {
    for (int i = blockIdx.x * blockDim.x + threadIdx.x; i < e;
         i += gridDim.x * blockDim.x) {
        int d = dst[i];
        int pos = atomicAdd(&g_cursor[d], 1);
        g_csrc[pos] = src[i];
    }
}

// ============================================================================
// K4: warp-per-node online-softmax aggregation over u (not h).
// Per-head softmax state lives in lanes 0-3; one exp warp-op per edge.
// z[n,h,:] = 0.25 * sum_e alpha_he u[src]   (head-mean folded)
// ============================================================================
__global__ __launch_bounds__(256) void k_gather(int nnodes)
{
    int gw = (blockIdx.x * blockDim.x + threadIdx.x) >> 5;
    if (gw >= nnodes) return;
    const int lane = threadIdx.x & 31;

    float adv = 0.f, m = 0.f, s = 0.f;
    if (lane < 4) {
        adv = g_adst[gw * 4 + lane];
        float t = g_asrc[gw * 4 + lane] + adv;     // self loop
        m = (t >= 0.f) ? t : NEG * t;
        s = 1.f;
    }
    float2 uself = ((const float2*)g_u)[(size_t)gw * 32 + lane];
    float2 A[4];
    #pragma unroll
    for (int h = 0; h < 4; h++) A[h] = uself;

    const int eb = g_rowptr[gw], ee = g_rowptr[gw + 1];
    for (int e = eb; e < ee; e++) {
        int src = g_csrc[e];
        float w = 0.f, sc = 1.f;
        if (lane < 4) {
            float t = g_asrc[src * 4 + lane] + adv;
            t = (t >= 0.f) ? t : NEG * t;
            float d = t - m;
            float ev = __expf(-fabsf(d));          // one MUFU covers both cases
            if (d > 0.f) { sc = ev; w = 1.f; m = t; s = s * ev + 1.f; }
            else         {          w = ev;         s = s + ev;       }
        }
        float2 us = ((const float2*)g_u)[(size_t)src * 32 + lane];
        #pragma unroll
        for (int h = 0; h < 4; h++) {
            float sch = __shfl_sync(0xffffffffu, sc, h);
            float wh  = __shfl_sync(0xffffffffu, w,  h);
            A[h].x = A[h].x * sch + wh * us.x;
            A[h].y = A[h].y * sch + wh * us.y;
        }
    }

    float inv = (lane < 4) ? 0.25f / s : 0.f;
    float2* z = (float2*)(g_z + (size_t)gw * 256);
    #pragma unroll
    for (int h = 0; h < 4; h++) {
        float ih = __shfl_sync(0xffffffffu, inv, h);
        z[h * 32 + lane] = make_float2(A[h].x * ih, A[h].y * ih);
    }
}

// ============================================================================
// K5: out = sum_h z_h W_gat_h^T    (256-row blocks, 8x8 microtiles)
// ============================================================================
#define K5_SMEM ((64*260 + 64*72) * 4)

__global__ __launch_bounds__(256) void k_gemm2(const float* __restrict__ Wgat,
                                               float* __restrict__ out, int n)
{
    extern __shared__ float sm[];
    float* sZ = sm;              // [64 k][260 rows]
    float* sB = sm + 64 * 260;   // [64 k][72 cols]
    const int tid = threadIdx.x;
    const int row0 = blockIdx.x * 256;
    const int r0 = (tid >> 3) << 3;
    const int cg = (tid & 7) << 3;

    float acc[8][8];
    #pragma unroll
    for (int a = 0; a < 8; a++)
        #pragma unroll
        for (int b = 0; b < 8; b++) acc[a][b] = 0.f;

    for (int c = 0; c < 4; c++) {
        for (int i = tid; i < 4096; i += 256) {
            int d = i >> 6, k = i & 63;
            sB[k * 72 + d] = Wgat[(c * 64 + d) * 64 + k];
        }
        for (int i = tid; i < 16384; i += 256) {
            int r = i >> 6, k = i & 63;
            int gr = row0 + r;
            sZ[k * 260 + r] = (gr < n) ? g_z[(size_t)gr * 256 + c * 64 + k] : 0.f;
        }
        __syncthreads();
        #pragma unroll 4
        for (int k = 0; k < 64; k++) {
            float4 a0 = *(const float4*)(sZ + k * 260 + r0);
            float4 a1 = *(const float4*)(sZ + k * 260 + r0 + 4);
            float4 b0 = *(const float4*)(sB + k * 72 + cg);
            float4 b1 = *(const float4*)(sB + k * 72 + cg + 4);
            float av[8] = {a0.x, a0.y, a0.z, a0.w, a1.x, a1.y, a1.z, a1.w};
            float bv[8] = {b0.x, b0.y, b0.z, b0.w, b1.x, b1.y, b1.z, b1.w};
            #pragma unroll
            for (int ri = 0; ri < 8; ri++)
                #pragma unroll
                for (int cj = 0; cj < 8; cj++) acc[ri][cj] += av[ri] * bv[cj];
        }
        __syncthreads();
    }

    #pragma unroll
    for (int ri = 0; ri < 8; ri++) {
        int gr = row0 + r0 + ri;
        if (gr < n) {
            *(float4*)(out + (size_t)gr * D + cg) =
                make_float4(acc[ri][0], acc[ri][1], acc[ri][2], acc[ri][3]);
            *(float4*)(out + (size_t)gr * D + cg + 4) =
                make_float4(acc[ri][4], acc[ri][5], acc[ri][6], acc[ri][7]);
        }
    }
}

// ============================================================================
// BatchNorm (batch stats; gat_bias cancels) + ReLU
// ============================================================================
__global__ void k_bnstats(const float* __restrict__ out, int nnodes) {
    __shared__ double shs[256], shq[256];
    const int c = threadIdx.x & 63;
    const int g = threadIdx.x >> 6;
    double s = 0.0, q = 0.0;
    for (int r = blockIdx.x * 4 + g; r < nnodes; r += gridDim.x * 4) {
        float v = out[(size_t)r * D + c];
        s += v;
        q += (double)v * v;
    }
    shs[threadIdx.x] = s; shq[threadIdx.x] = q;
    __syncthreads();
    if (g == 0) {
        s = shs[c] + shs[c + 64] + shs[c + 128] + shs[c + 192];
        q = shq[c] + shq[c + 64] + shq[c + 128] + shq[c + 192];
        atomicAdd(&g_sums[c], s);
        atomicAdd(&g_sums[64 + c], q);
    }
}

__global__ void k_bnprep(const float* __restrict__ gamma,
                         const float* __restrict__ beta, int nnodes) {
    int c = threadIdx.x;
    if (c < 64) {
        double mean = g_sums[c] / nnodes;
        double var  = g_sums[64 + c] / nnodes - mean * mean;
        float scale = gamma[c] * rsqrtf((float)var + BN_EPS);
        g_bnsc[c] = scale;
        g_bnsh[c] = beta[c] - (float)mean * scale;
    }
}

__global__ void k_bnfinal(float* __restrict__ out, int nnodes) {
    int i = blockIdx.x * blockDim.x + threadIdx.x;
    int total = nnodes * 16;
    if (i >= total) return;
    int c4 = (i & 15) << 2;
    float4 v = ((float4*)out)[i];
    float4 sc = *(const float4*)(g_bnsc + c4);
    float4 sh = *(const float4*)(g_bnsh + c4);
    v.x = fmaxf(0.f, v.x * sc.x + sh.x);
    v.y = fmaxf(0.f, v.y * sc.y + sh.y);
    v.z = fmaxf(0.f, v.z * sc.z + sh.z);
    v.w = fmaxf(0.f, v.w * sc.w + sh.w);
    ((float4*)out)[i] = v;
}

// ============================================================================
extern "C" void kernel_launch(void* const* d_in, const int* in_sizes, int n_in,
                              void* d_out, int out_size)
{
    const float* x    = (const float*)d_in[0];
    const int*   ei   = (const int*)  d_in[1];
    const float* Wlin = (const float*)d_in[2];
    const float* blin = (const float*)d_in[3];
    const float* pw   = (const float*)d_in[4];
    const float* Wgat = (const float*)d_in[5];
    const float* attS = (const float*)d_in[6];
    const float* attD = (const float*)d_in[7];
    // d_in[8] = gat_bias: cancels under batch-stat BatchNorm.
    const float* gamma = (const float*)d_in[9];
    const float* beta  = (const float*)d_in[10];
    float* out = (float*)d_out;

    int n = in_sizes[0] / D;     // 50000
    int e = in_sizes[1] / 2;     // 800000
    const int* srcA = ei;
    const int* dstA = ei + e;

    static int inited = 0;
    if (!inited) {
        cudaFuncSetAttribute(k_linear, cudaFuncAttributeMaxDynamicSharedMemorySize, K1_SMEM);
        cudaFuncSetAttribute(k_gemm2,  cudaFuncAttributeMaxDynamicSharedMemorySize, K5_SMEM);
        inited = 1;
    }

    k_prep<<<1, 256>>>(Wgat, attS, attD);
    k_linear<<<(n + 63) / 64, 256, K1_SMEM>>>(x, Wlin, blin, pw, n);

    k_zero_cnt<<<(n + 255) / 256, 256>>>(n);
    k_hist<<<1024, 256>>>(dstA, e);
    int nch = (n + 511) / 512;
    k_scanA<<<nch, 512>>>(n);
    k_scanB<<<1, 256>>>(nch);
    k_scanC<<<(n + 255) / 256, 256>>>(n, e);
    k_scatter<<<1024, 256>>>(srcA, dstA, e);

    k_gather<<<(n * 32 + 255) / 256, 256>>>(n);

    k_gemm2<<<(n + 255) / 256, 256, K5_SMEM>>>(Wgat, out, n);

    k_bnstats<<<200, 256>>>(out, n);
    k_bnprep<<<1, 64>>>(gamma, beta, n);
    k_bnfinal<<<(n * 16 + 255) / 256, 256>>>(out, n);
}

// round 3
// speedup vs baseline: 1.0498x; 1.0498x over previous
#include <cuda_runtime.h>
#include <cstdint>
#include <cstddef>

#define D   64
#define H   4
#define NEG 0.2f
#define BN_EPS 1e-5f

#define NMAX 50000
#define EMAX 800000

// ---------------- scratch (static device globals; no allocation) ----------------
__device__ float  g_u[(size_t)NMAX * D];        // [N,64] post-PReLU features
__device__ float  g_z[(size_t)NMAX * 256];      // [N,H,64] aggregated (head-scaled)
__device__ float  g_asrc[NMAX * H];
__device__ float  g_adst[NMAX * H];
__device__ float  g_w[(size_t)EMAX * H];        // per-edge softmax numerators
__device__ float  g_wself[NMAX * H];
__device__ float  g_dnm[NMAX * H];              // 0.25/denominator
__device__ float  g_cs[H * D];                  // W_gat_h^T att_src_h
__device__ float  g_cd[H * D];                  // W_gat_h^T att_dst_h
__device__ int    g_cnt[NMAX];
__device__ int    g_rowptr[NMAX + 1];
__device__ int    g_cursor[NMAX];
__device__ int    g_csrc[EMAX];
__device__ int    g_bsum[256];
__device__ double g_sums[128];                  // [0:64) sum, [64:128) sumsq
__device__ float  g_bnsc[64], g_bnsh[64];

// ---------------- fast exp: FMA polynomial (avoids MUFU pipe) ----------------
__device__ __forceinline__ float fexp(float x) {
    x = fmaxf(x, -80.f);
    float y  = x * 1.44269504089f;
    float t  = y + 12582912.0f;                  // round-to-nearest int
    int   ki = __float_as_int(t) - 0x4B400000;
    float r  = y - (t - 12582912.0f);
    float p  = 1.5403530e-4f;
    p = fmaf(p, r, 1.3333558e-3f);
    p = fmaf(p, r, 9.6181291e-3f);
    p = fmaf(p, r, 5.5504109e-2f);
    p = fmaf(p, r, 2.4022651e-1f);
    p = fmaf(p, r, 6.9314718e-1f);
    p = fmaf(p, r, 1.0f);
    return __int_as_float(__float_as_int(p) + (ki << 23));
}

__device__ __forceinline__ float lrelu(float v) { return (v >= 0.f) ? v : NEG * v; }

// ============================================================================
// K0: c_src/c_dst projection vectors + zero sums prep
// ============================================================================
__global__ void k_prep(const float* __restrict__ Wgat,
                       const float* __restrict__ attS,
                       const float* __restrict__ attD) {
    int tid = threadIdx.x;              // 256
    if (tid < 128) g_sums[tid] = 0.0;
    int h = tid >> 6, k = tid & 63;
    float s = 0.f, d2 = 0.f;
    #pragma unroll 8
    for (int dd = 0; dd < 64; dd++) {
        float wv = Wgat[(h * 64 + dd) * 64 + k];
        s  += attS[h * 64 + dd] * wv;
        d2 += attD[h * 64 + dd] * wv;
    }
    g_cs[tid] = s;
    g_cd[tid] = d2;
}

// ============================================================================
// K1: u = PReLU(x W_lin^T + b); a_src = u.c_s; a_dst = u.c_d
// ============================================================================
#define K1_SMEM ((3*64*72 + 2*4*68) * 4)

__global__ __launch_bounds__(256) void k_linear(
    const float* __restrict__ x, const float* __restrict__ Wlin,
    const float* __restrict__ blin, const float* __restrict__ pw, int nrows)
{
    extern __shared__ float sm[];
    float* sX = sm;                  // [64][72]  xT
    float* sU = sm + 64 * 72;        // [64][72]  uT
    float* sW = sm + 2 * 64 * 72;    // [64][72]  Wlin^T
    float* sC  = sm + 3 * 64 * 72;   // [4][68]
    float* sC2 = sC + 4 * 68;        // [4][68]
    const int tid  = threadIdx.x;
    const int row0 = blockIdx.x * 64;

    {
        int h = tid >> 6, k = tid & 63;
        sC [h * 68 + k] = g_cs[tid];
        sC2[h * 68 + k] = g_cd[tid];
    }
    for (int i = tid; i < 64 * 64; i += 256) {
        int r = i >> 6, k = i & 63;
        int gr = row0 + r;
        sX[k * 72 + r] = (gr < nrows) ? x[(size_t)gr * D + k] : 0.f;
    }
    for (int i = tid; i < 64 * 64; i += 256) {
        int j = i >> 6, k = i & 63;
        sW[k * 72 + j] = Wlin[i];
    }
    __syncthreads();

    {
        const int rg = (tid >> 4) << 2;
        const int cg = (tid & 15) << 2;
        float acc[4][4];
        #pragma unroll
        for (int a = 0; a < 4; a++)
            #pragma unroll
            for (int b = 0; b < 4; b++) acc[a][b] = 0.f;
        #pragma unroll 8
        for (int k = 0; k < 64; k++) {
            float4 a4 = *(const float4*)(sX + k * 72 + rg);
            float4 b4 = *(const float4*)(sW + k * 72 + cg);
            float av[4] = {a4.x, a4.y, a4.z, a4.w};
            float bv[4] = {b4.x, b4.y, b4.z, b4.w};
            #pragma unroll
            for (int ri = 0; ri < 4; ri++)
                #pragma unroll
                for (int cj = 0; cj < 4; cj++) acc[ri][cj] += av[ri] * bv[cj];
        }
        float4 bb = *(const float4*)(blin + cg);
        float4 pp = *(const float4*)(pw + cg);
        float bvb[4] = {bb.x, bb.y, bb.z, bb.w};
        float pvb[4] = {pp.x, pp.y, pp.z, pp.w};
        #pragma unroll
        for (int ri = 0; ri < 4; ri++) {
            float v4[4];
            #pragma unroll
            for (int cj = 0; cj < 4; cj++) {
                float v = acc[ri][cj] + bvb[cj];
                v = (v >= 0.f) ? v : pvb[cj] * v;
                sU[(cg + cj) * 72 + rg + ri] = v;
                v4[cj] = v;
            }
            int gr = row0 + rg + ri;
            if (gr < nrows)
                *(float4*)(g_u + (size_t)gr * D + cg) =
                    make_float4(v4[0], v4[1], v4[2], v4[3]);
        }
    }
    __syncthreads();

    {
        const int r = tid >> 2, h = tid & 3;
        float sa = 0.f, da = 0.f;
        #pragma unroll 8
        for (int k = 0; k < 64; k++) {
            float uv = sU[k * 72 + r];
            sa += uv * sC [h * 68 + k];
            da += uv * sC2[h * 68 + k];
        }
        int gr = row0 + r;
        if (gr < nrows) {
            g_asrc[gr * 4 + h] = sa;
            g_adst[gr * 4 + h] = da;
        }
    }
}

// ============================================================================
// CSR build
// ============================================================================
__global__ void k_zero_cnt(int n) {
    int i = blockIdx.x * blockDim.x + threadIdx.x;
    if (i < n) g_cnt[i] = 0;
}

__global__ void k_hist(const int* __restrict__ dst, int e) {
    for (int i = blockIdx.x * blockDim.x + threadIdx.x; i < e;
         i += gridDim.x * blockDim.x)
        atomicAdd(&g_cnt[dst[i]], 1);
}

__global__ void k_scanA(int n) {
    __shared__ int sh[512];
    int i = blockIdx.x * 512 + threadIdx.x;
    int v = (i < n) ? g_cnt[i] : 0;
    sh[threadIdx.x] = v;
    __syncthreads();
    #pragma unroll
    for (int off = 1; off < 512; off <<= 1) {
        int t = (threadIdx.x >= off) ? sh[threadIdx.x - off] : 0;
        __syncthreads();
        sh[threadIdx.x] += t;
        __syncthreads();
    }
    if (i < n) g_rowptr[i] = sh[threadIdx.x] - v;
    if (threadIdx.x == 511) g_bsum[blockIdx.x] = sh[511];
}

__global__ void k_scanB(int nch) {
    __shared__ int sh[256];
    int v = (threadIdx.x < nch) ? g_bsum[threadIdx.x] : 0;
    sh[threadIdx.x] = v;
    __syncthreads();
    #pragma unroll
    for (int off = 1; off < 256; off <<= 1) {
        int t = (threadIdx.x >= off) ? sh[threadIdx.x - off] : 0;
        __syncthreads();
        sh[threadIdx.x] += t;
        __syncthreads();
    }
    if (threadIdx.x < nch) g_bsum[threadIdx.x] = sh[threadIdx.x] - v;
}

__global__ void k_scanC(int n, int e) {
    int i = blockIdx.x * blockDim.x + threadIdx.x;
    if (i < n) {
        int v = g_rowptr[i] + g_bsum[i >> 9];
        g_rowptr[i] = v;
        g_cursor[i] = v;
    }
    if (i == 0) g_rowptr[n] = e;
}

__global__ void k_scatter(const int* __restrict__ src, const int* __restrict__ dst, int e) {
    for (int i = blockIdx.x * blockDim.x + threadIdx.x; i < e;
         i += gridDim.x * blockDim.x) {
        int d = dst[i];
        int pos = atomicAdd(&g_cursor[d], 1);
        g_csrc[pos] = src[i];
    }
}

// ============================================================================
// K4a: per-node softmax (lanes parallel over edges, no serial chain).
// Pass 1: max. Pass 2: w=exp(lv-m) stored per edge + denominator reduce.
// ============================================================================
__global__ __launch_bounds__(256) void k_alpha(int n)
{
    int gw = (blockIdx.x * blockDim.x + threadIdx.x) >> 5;
    if (gw >= n) return;
    const int lane = threadIdx.x & 31;

    float4 adv = ((const float4*)g_adst)[gw];
    float4 sv  = ((const float4*)g_asrc)[gw];
    float4 ls  = make_float4(lrelu(sv.x + adv.x), lrelu(sv.y + adv.y),
                             lrelu(sv.z + adv.z), lrelu(sv.w + adv.w));
    float4 mx = ls;
    const int eb = g_rowptr[gw], ee = g_rowptr[gw + 1];

    for (int e = eb + lane; e < ee; e += 32) {
        float4 a = ((const float4*)g_asrc)[g_csrc[e]];
        mx.x = fmaxf(mx.x, lrelu(a.x + adv.x));
        mx.y = fmaxf(mx.y, lrelu(a.y + adv.y));
        mx.z = fmaxf(mx.z, lrelu(a.z + adv.z));
        mx.w = fmaxf(mx.w, lrelu(a.w + adv.w));
    }
    #pragma unroll
    for (int off = 16; off; off >>= 1) {
        mx.x = fmaxf(mx.x, __shfl_xor_sync(0xffffffffu, mx.x, off));
        mx.y = fmaxf(mx.y, __shfl_xor_sync(0xffffffffu, mx.y, off));
        mx.z = fmaxf(mx.z, __shfl_xor_sync(0xffffffffu, mx.z, off));
        mx.w = fmaxf(mx.w, __shfl_xor_sync(0xffffffffu, mx.w, off));
    }

    float4 wself = make_float4(fexp(ls.x - mx.x), fexp(ls.y - mx.y),
                               fexp(ls.z - mx.z), fexp(ls.w - mx.w));
    float4 acc = (lane == 0) ? wself : make_float4(0.f, 0.f, 0.f, 0.f);

    for (int e = eb + lane; e < ee; e += 32) {
        float4 a = ((const float4*)g_asrc)[g_csrc[e]];
        float4 w = make_float4(fexp(lrelu(a.x + adv.x) - mx.x),
                               fexp(lrelu(a.y + adv.y) - mx.y),
                               fexp(lrelu(a.z + adv.z) - mx.z),
                               fexp(lrelu(a.w + adv.w) - mx.w));
        ((float4*)g_w)[e] = w;
        acc.x += w.x; acc.y += w.y; acc.z += w.z; acc.w += w.w;
    }
    #pragma unroll
    for (int off = 16; off; off >>= 1) {
        acc.x += __shfl_xor_sync(0xffffffffu, acc.x, off);
        acc.y += __shfl_xor_sync(0xffffffffu, acc.y, off);
        acc.z += __shfl_xor_sync(0xffffffffu, acc.z, off);
        acc.w += __shfl_xor_sync(0xffffffffu, acc.w, off);
    }
    if (lane == 0) {
        ((float4*)g_wself)[gw] = wself;
        ((float4*)g_dnm)[gw]   = make_float4(0.25f / acc.x, 0.25f / acc.y,
                                             0.25f / acc.z, 0.25f / acc.w);
    }
}

// ============================================================================
// K4b: weighted gather. Warp-per-node, lanes over dims. Pure pipelined FMAs.
// ============================================================================
__global__ __launch_bounds__(256) void k_gatherB(int n)
{
    int gw = (blockIdx.x * blockDim.x + threadIdx.x) >> 5;
    if (gw >= n) return;
    const int lane = threadIdx.x & 31;

    float4 ws = ((const float4*)g_wself)[gw];
    float2 us = ((const float2*)g_u)[(size_t)gw * 32 + lane];
    float2 A0 = make_float2(ws.x * us.x, ws.x * us.y);
    float2 A1 = make_float2(ws.y * us.x, ws.y * us.y);
    float2 A2 = make_float2(ws.z * us.x, ws.z * us.y);
    float2 A3 = make_float2(ws.w * us.x, ws.w * us.y);

    const int eb = g_rowptr[gw], ee = g_rowptr[gw + 1];
    #pragma unroll 4
    for (int e = eb; e < ee; e++) {
        int src  = g_csrc[e];
        float4 w = ((const float4*)g_w)[e];
        float2 uv = ((const float2*)g_u)[(size_t)src * 32 + lane];
        A0.x = fmaf(w.x, uv.x, A0.x); A0.y = fmaf(w.x, uv.y, A0.y);
        A1.x = fmaf(w.y, uv.x, A1.x); A1.y = fmaf(w.y, uv.y, A1.y);
        A2.x = fmaf(w.z, uv.x, A2.x); A2.y = fmaf(w.z, uv.y, A2.y);
        A3.x = fmaf(w.w, uv.x, A3.x); A3.y = fmaf(w.w, uv.y, A3.y);
    }

    float4 dn = ((const float4*)g_dnm)[gw];
    float2* z = (float2*)(g_z + (size_t)gw * 256);
    z[0 * 32 + lane] = make_float2(A0.x * dn.x, A0.y * dn.x);
    z[1 * 32 + lane] = make_float2(A1.x * dn.y, A1.y * dn.y);
    z[2 * 32 + lane] = make_float2(A2.x * dn.z, A2.y * dn.z);
    z[3 * 32 + lane] = make_float2(A3.x * dn.w, A3.y * dn.w);
}

// ============================================================================
// K5: out = sum_h z_h W_gat_h^T
// ============================================================================
#define K5_SMEM ((64*260 + 64*72) * 4)

__global__ __launch_bounds__(256) void k_gemm2(const float* __restrict__ Wgat,
                                               float* __restrict__ out, int n)
{
    extern __shared__ float sm[];
    float* sZ = sm;              // [64 k][260 rows]
    float* sB = sm + 64 * 260;   // [64 k][72 cols]
    const int tid = threadIdx.x;
    const int row0 = blockIdx.x * 256;
    const int r0 = (tid >> 3) << 3;
    const int cg = (tid & 7) << 3;

    float acc[8][8];
    #pragma unroll
    for (int a = 0; a < 8; a++)
        #pragma unroll
        for (int b = 0; b < 8; b++) acc[a][b] = 0.f;

    for (int c = 0; c < 4; c++) {
        for (int i = tid; i < 4096; i += 256) {
            int d = i >> 6, k = i & 63;
            sB[k * 72 + d] = Wgat[(c * 64 + d) * 64 + k];
        }
        for (int i = tid; i < 16384; i += 256) {
            int r = i >> 6, k = i & 63;
            int gr = row0 + r;
            sZ[k * 260 + r] = (gr < n) ? g_z[(size_t)gr * 256 + c * 64 + k] : 0.f;
        }
        __syncthreads();
        #pragma unroll 4
        for (int k = 0; k < 64; k++) {
            float4 a0 = *(const float4*)(sZ + k * 260 + r0);
            float4 a1 = *(const float4*)(sZ + k * 260 + r0 + 4);
            float4 b0 = *(const float4*)(sB + k * 72 + cg);
            float4 b1 = *(const float4*)(sB + k * 72 + cg + 4);
            float av[8] = {a0.x, a0.y, a0.z, a0.w, a1.x, a1.y, a1.z, a1.w};
            float bv[8] = {b0.x, b0.y, b0.z, b0.w, b1.x, b1.y, b1.z, b1.w};
            #pragma unroll
            for (int ri = 0; ri < 8; ri++)
                #pragma unroll
                for (int cj = 0; cj < 8; cj++) acc[ri][cj] += av[ri] * bv[cj];
        }
        __syncthreads();
    }

    #pragma unroll
    for (int ri = 0; ri < 8; ri++) {
        int gr = row0 + r0 + ri;
        if (gr < n) {
            *(float4*)(out + (size_t)gr * D + cg) =
                make_float4(acc[ri][0], acc[ri][1], acc[ri][2], acc[ri][3]);
            *(float4*)(out + (size_t)gr * D + cg + 4) =
                make_float4(acc[ri][4], acc[ri][5], acc[ri][6], acc[ri][7]);
        }
    }
}

// ============================================================================
// BatchNorm (batch stats; gat_bias cancels) + ReLU
// ============================================================================
__global__ void k_bnstats(const float* __restrict__ out, int nnodes) {
    __shared__ double shs[256], shq[256];
    const int c = threadIdx.x & 63;
    const int g = threadIdx.x >> 6;
    double s = 0.0, q = 0.0;
    for (int r = blockIdx.x * 4 + g; r < nnodes; r += gridDim.x * 4) {
        float v = out[(size_t)r * D + c];
        s += v;
        q += (double)v * v;
    }
    shs[threadIdx.x] = s; shq[threadIdx.x] = q;
    __syncthreads();
    if (g == 0) {
        s = shs[c] + shs[c + 64] + shs[c + 128] + shs[c + 192];
        q = shq[c] + shq[c + 64] + shq[c + 128] + shq[c + 192];
        atomicAdd(&g_sums[c], s);
        atomicAdd(&g_sums[64 + c], q);
    }
}

__global__ void k_bnprep(const float* __restrict__ gamma,
                         const float* __restrict__ beta, int nnodes) {
    int c = threadIdx.x;
    if (c < 64) {
        double mean = g_sums[c] / nnodes;
        double var  = g_sums[64 + c] / nnodes - mean * mean;
        float scale = gamma[c] * rsqrtf((float)var + BN_EPS);
        g_bnsc[c] = scale;
        g_bnsh[c] = beta[c] - (float)mean * scale;
    }
}

__global__ void k_bnfinal(float* __restrict__ out, int nnodes) {
    int i = blockIdx.x * blockDim.x + threadIdx.x;
    int total = nnodes * 16;
    if (i >= total) return;
    int c4 = (i & 15) << 2;
    float4 v = ((float4*)out)[i];
    float4 sc = *(const float4*)(g_bnsc + c4);
    float4 sh = *(const float4*)(g_bnsh + c4);
    v.x = fmaxf(0.f, v.x * sc.x + sh.x);
    v.y = fmaxf(0.f, v.y * sc.y + sh.y);
    v.z = fmaxf(0.f, v.z * sc.z + sh.z);
    v.w = fmaxf(0.f, v.w * sc.w + sh.w);
    ((float4*)out)[i] = v;
}

// ============================================================================
extern "C" void kernel_launch(void* const* d_in, const int* in_sizes, int n_in,
                              void* d_out, int out_size)
{
    const float* x    = (const float*)d_in[0];
    const int*   ei   = (const int*)  d_in[1];
    const float* Wlin = (const float*)d_in[2];
    const float* blin = (const float*)d_in[3];
    const float* pw   = (const float*)d_in[4];
    const float* Wgat = (const float*)d_in[5];
    const float* attS = (const float*)d_in[6];
    const float* attD = (const float*)d_in[7];
    // d_in[8] = gat_bias: cancels under batch-stat BatchNorm.
    const float* gamma = (const float*)d_in[9];
    const float* beta  = (const float*)d_in[10];
    float* out = (float*)d_out;

    int n = in_sizes[0] / D;     // 50000
    int e = in_sizes[1] / 2;     // 800000
    const int* srcA = ei;
    const int* dstA = ei + e;

    static int inited = 0;
    if (!inited) {
        cudaFuncSetAttribute(k_linear, cudaFuncAttributeMaxDynamicSharedMemorySize, K1_SMEM);
        cudaFuncSetAttribute(k_gemm2,  cudaFuncAttributeMaxDynamicSharedMemorySize, K5_SMEM);
        inited = 1;
    }

    k_prep<<<1, 256>>>(Wgat, attS, attD);
    k_linear<<<(n + 63) / 64, 256, K1_SMEM>>>(x, Wlin, blin, pw, n);

    k_zero_cnt<<<(n + 255) / 256, 256>>>(n);
    k_hist<<<1024, 256>>>(dstA, e);
    int nch = (n + 511) / 512;
    k_scanA<<<nch, 512>>>(n);
    k_scanB<<<1, 256>>>(nch);
    k_scanC<<<(n + 255) / 256, 256>>>(n, e);
    k_scatter<<<1024, 256>>>(srcA, dstA, e);

    k_alpha<<<(n * 32 + 255) / 256, 256>>>(n);
    k_gatherB<<<(n * 32 + 255) / 256, 256>>>(n);

    k_gemm2<<<(n + 255) / 256, 256, K5_SMEM>>>(Wgat, out, n);

    k_bnstats<<<200, 256>>>(out, n);
    k_bnprep<<<1, 64>>>(gamma, beta, n);
    k_bnfinal<<<(n * 16 + 255) / 256, 256>>>(out, n);
}

// round 4
// speedup vs baseline: 1.5426x; 1.4695x over previous
#include <cuda_runtime.h>
#include <cstdint>
#include <cstddef>

#define D   64
#define H   4
#define NEG 0.2f
#define BN_EPS 1e-5f

#define NMAX 50000
#define EMAX 800000

// ---------------- scratch (static device globals; no allocation) ----------------
__device__ float  g_h[(size_t)NMAX * 256];      // [N,H,64] GAT-transformed features
__device__ float  g_asrc[NMAX * H];
__device__ float  g_adst[NMAX * H];
__device__ float  g_w[(size_t)EMAX * H];        // per-edge softmax numerators (edge order)
__device__ float  g_wcsr[(size_t)EMAX * H];     // per-edge weights (CSR order)
__device__ float  g_wself[NMAX * H];
__device__ float  g_dnm[NMAX * H];              // softmax denominators (atomic)
__device__ float  g_cs[H * D];                  // W_gat_h^T att_src_h
__device__ float  g_cd[H * D];                  // W_gat_h^T att_dst_h
__device__ int    g_cnt[NMAX];
__device__ int    g_rowptr[NMAX + 1];
__device__ int    g_cursor[NMAX];
__device__ int    g_csrc[EMAX];
__device__ int    g_bsum[256];
__device__ double g_sums[128];                  // [0:64) sum, [64:128) sumsq
__device__ float  g_bnsc[64], g_bnsh[64];

// ---------------- fast exp: FMA polynomial (no MUFU) ----------------
__device__ __forceinline__ float fexp(float x) {
    x = fmaxf(x, -80.f);
    float y  = x * 1.44269504089f;
    float t  = y + 12582912.0f;                  // round-to-nearest int
    int   ki = __float_as_int(t) - 0x4B400000;
    float r  = y - (t - 12582912.0f);
    float p  = 1.5403530e-4f;
    p = fmaf(p, r, 1.3333558e-3f);
    p = fmaf(p, r, 9.6181291e-3f);
    p = fmaf(p, r, 5.5504109e-2f);
    p = fmaf(p, r, 2.4022651e-1f);
    p = fmaf(p, r, 6.9314718e-1f);
    p = fmaf(p, r, 1.0f);
    return __int_as_float(__float_as_int(p) + (ki << 23));
}

__device__ __forceinline__ float lrelu(float v) { return (v >= 0.f) ? v : NEG * v; }

// ============================================================================
// K0: zero counters/denoms/sums + c_src/c_dst projection vectors
// ============================================================================
__global__ void k_prep(const float* __restrict__ Wgat,
                       const float* __restrict__ attS,
                       const float* __restrict__ attD, int n) {
    int gid = blockIdx.x * blockDim.x + threadIdx.x;
    int stride = gridDim.x * blockDim.x;
    for (int i = gid; i < n; i += stride) g_cnt[i] = 0;
    for (int i = gid; i < n * 4; i += stride) g_dnm[i] = 0.f;
    if (blockIdx.x == 0) {
        int tid = threadIdx.x;
        if (tid < 128) g_sums[tid] = 0.0;
        int h = tid >> 6, k = tid & 63;
        float s = 0.f, d2 = 0.f;
        #pragma unroll 8
        for (int dd = 0; dd < 64; dd++) {
            float wv = Wgat[(h * 64 + dd) * 64 + k];
            s  += attS[h * 64 + dd] * wv;
            d2 += attD[h * 64 + dd] * wv;
        }
        g_cs[tid] = s;
        g_cd[tid] = d2;
    }
}

// ============================================================================
// K1: fused  u = PReLU(x W_lin^T + b);  h = u W_gat^T;  a_src/a_dst dots;
//     + destination histogram (grid-stride, overlaps with FFMA work)
// ============================================================================
#define K1_SMEM ((2*64*72 + 64*264 + 2*4*68) * 4)

__global__ __launch_bounds__(256) void k_linear(
    const float* __restrict__ x, const float* __restrict__ Wlin,
    const float* __restrict__ blin, const float* __restrict__ pw,
    const int* __restrict__ dstA, int nrows, int nedges)
{
    extern __shared__ float sm[];
    float* sX  = sm;                     // [64][72]  xT
    float* sU  = sm + 64 * 72;           // [64][72]  uT
    float* sW  = sm + 2 * 64 * 72;       // [64][264] weights transposed [k][out]
    float* sC  = sm + 2 * 64 * 72 + 64 * 264;   // [4][68]
    float* sC2 = sC + 4 * 68;                   // [4][68]
    const int tid  = threadIdx.x;
    const int row0 = blockIdx.x * 64;

    // histogram of destinations (independent work, overlaps)
    {
        int gid = blockIdx.x * 256 + tid;
        int stride = gridDim.x * 256;
        for (int i = gid; i < nedges; i += stride)
            atomicAdd(&g_cnt[dstA[i]], 1);
    }

    {
        int h = tid >> 6, k = tid & 63;
        sC [h * 68 + k] = g_cs[tid];
        sC2[h * 68 + k] = g_cd[tid];
    }
    for (int i = tid; i < 64 * 64; i += 256) {
        int r = i >> 6, k = i & 63;
        int gr = row0 + r;
        sX[k * 72 + r] = (gr < nrows) ? x[(size_t)gr * D + k] : 0.f;
    }
    for (int i = tid; i < 64 * 64; i += 256) {
        int j = i >> 6, k = i & 63;
        sW[k * 264 + j] = Wlin[i];
    }
    __syncthreads();

    // ---- stage A: u = PReLU(x W_lin^T + b) -> sU (transposed) ----
    {
        const int rg = (tid >> 4) << 2;
        const int cg = (tid & 15) << 2;
        float acc[4][4];
        #pragma unroll
        for (int a = 0; a < 4; a++)
            #pragma unroll
            for (int b = 0; b < 4; b++) acc[a][b] = 0.f;
        #pragma unroll 8
        for (int k = 0; k < 64; k++) {
            float4 a4 = *(const float4*)(sX + k * 72 + rg);
            float4 b4 = *(const float4*)(sW + k * 264 + cg);
            float av[4] = {a4.x, a4.y, a4.z, a4.w};
            float bv[4] = {b4.x, b4.y, b4.z, b4.w};
            #pragma unroll
            for (int ri = 0; ri < 4; ri++)
                #pragma unroll
                for (int cj = 0; cj < 4; cj++) acc[ri][cj] += av[ri] * bv[cj];
        }
        float4 bb = *(const float4*)(blin + cg);
        float4 pp = *(const float4*)(pw + cg);
        float bvb[4] = {bb.x, bb.y, bb.z, bb.w};
        float pvb[4] = {pp.x, pp.y, pp.z, pp.w};
        #pragma unroll
        for (int ri = 0; ri < 4; ri++)
            #pragma unroll
            for (int cj = 0; cj < 4; cj++) {
                float v = acc[ri][cj] + bvb[cj];
                v = (v >= 0.f) ? v : pvb[cj] * v;
                sU[(cg + cj) * 72 + rg + ri] = v;
            }
    }
    __syncthreads();
    // load W_gat transposed: Wgat is at sW (reuse): done by reloading from gmem
    // (W_gat passed via g_cs? no — reload from global through const path)
    // NOTE: Wgat pointer passed in via global scratch trick not needed; we pass it
    // as kernel arg below.
    __syncthreads();
}

// Second half of K1 split is avoided: define the real fused kernel with Wgat arg.
__global__ __launch_bounds__(256) void k_linear2(
    const float* __restrict__ x, const float* __restrict__ Wlin,
    const float* __restrict__ blin, const float* __restrict__ pw,
    const float* __restrict__ Wgat, const int* __restrict__ dstA,
    int nrows, int nedges)
{
    extern __shared__ float sm[];
    float* sX  = sm;                     // [64][72]
    float* sU  = sm + 64 * 72;           // [64][72]
    float* sW  = sm + 2 * 64 * 72;       // [64][264]
    float* sC  = sm + 2 * 64 * 72 + 64 * 264;   // [4][68]
    float* sC2 = sC + 4 * 68;                   // [4][68]
    const int tid  = threadIdx.x;
    const int row0 = blockIdx.x * 64;

    {
        int gid = blockIdx.x * 256 + tid;
        int stride = gridDim.x * 256;
        for (int i = gid; i < nedges; i += stride)
            atomicAdd(&g_cnt[dstA[i]], 1);
    }

    {
        int h = tid >> 6, k = tid & 63;
        sC [h * 68 + k] = g_cs[tid];
        sC2[h * 68 + k] = g_cd[tid];
    }
    for (int i = tid; i < 64 * 64; i += 256) {
        int r = i >> 6, k = i & 63;
        int gr = row0 + r;
        sX[k * 72 + r] = (gr < nrows) ? x[(size_t)gr * D + k] : 0.f;
    }
    for (int i = tid; i < 64 * 64; i += 256) {
        int j = i >> 6, k = i & 63;
        sW[k * 264 + j] = Wlin[i];
    }
    __syncthreads();

    // ---- stage A ----
    {
        const int rg = (tid >> 4) << 2;
        const int cg = (tid & 15) << 2;
        float acc[4][4];
        #pragma unroll
        for (int a = 0; a < 4; a++)
            #pragma unroll
            for (int b = 0; b < 4; b++) acc[a][b] = 0.f;
        #pragma unroll 8
        for (int k = 0; k < 64; k++) {
            float4 a4 = *(const float4*)(sX + k * 72 + rg);
            float4 b4 = *(const float4*)(sW + k * 264 + cg);
            float av[4] = {a4.x, a4.y, a4.z, a4.w};
            float bv[4] = {b4.x, b4.y, b4.z, b4.w};
            #pragma unroll
            for (int ri = 0; ri < 4; ri++)
                #pragma unroll
                for (int cj = 0; cj < 4; cj++) acc[ri][cj] += av[ri] * bv[cj];
        }
        float4 bb = *(const float4*)(blin + cg);
        float4 pp = *(const float4*)(pw + cg);
        float bvb[4] = {bb.x, bb.y, bb.z, bb.w};
        float pvb[4] = {pp.x, pp.y, pp.z, pp.w};
        #pragma unroll
        for (int ri = 0; ri < 4; ri++)
            #pragma unroll
            for (int cj = 0; cj < 4; cj++) {
                float v = acc[ri][cj] + bvb[cj];
                v = (v >= 0.f) ? v : pvb[cj] * v;
                sU[(cg + cj) * 72 + rg + ri] = v;
            }
    }
    __syncthreads();
    for (int i = tid; i < 256 * 64; i += 256) {
        int m = i >> 6, k = i & 63;
        sW[k * 264 + m] = Wgat[i];
    }
    __syncthreads();

    // ---- stage B: h = u W_gat^T (8x8 micro-tiles) ----
    const int lane = tid & 31;
    const int r0   = (tid >> 5) << 3;
    const int mlo  = lane << 2;
    const int mhi  = 128 + mlo;
    float acc[8][8];
    #pragma unroll
    for (int a = 0; a < 8; a++)
        #pragma unroll
        for (int b = 0; b < 8; b++) acc[a][b] = 0.f;

    #pragma unroll 8
    for (int k = 0; k < 64; k++) {
        float4 a0 = *(const float4*)(sU + k * 72 + r0);
        float4 a1 = *(const float4*)(sU + k * 72 + r0 + 4);
        float4 b0 = *(const float4*)(sW + k * 264 + mlo);
        float4 b1 = *(const float4*)(sW + k * 264 + mhi);
        float av[8] = {a0.x, a0.y, a0.z, a0.w, a1.x, a1.y, a1.z, a1.w};
        float bv[8] = {b0.x, b0.y, b0.z, b0.w, b1.x, b1.y, b1.z, b1.w};
        #pragma unroll
        for (int ri = 0; ri < 8; ri++)
            #pragma unroll
            for (int cj = 0; cj < 8; cj++) acc[ri][cj] += av[ri] * bv[cj];
    }
    #pragma unroll
    for (int ri = 0; ri < 8; ri++) {
        int gr = row0 + r0 + ri;
        if (gr < nrows) {
            *(float4*)(g_h + (size_t)gr * 256 + mlo) =
                make_float4(acc[ri][0], acc[ri][1], acc[ri][2], acc[ri][3]);
            *(float4*)(g_h + (size_t)gr * 256 + mhi) =
                make_float4(acc[ri][4], acc[ri][5], acc[ri][6], acc[ri][7]);
        }
    }

    // ---- attention dots from sU (no extra sync needed: sU read-only here) ----
    {
        const int r = tid >> 2, h = tid & 3;
        float sa = 0.f, da = 0.f;
        #pragma unroll 8
        for (int k = 0; k < 64; k++) {
            float uv = sU[k * 72 + r];
            sa += uv * sC [h * 68 + k];
            da += uv * sC2[h * 68 + k];
        }
        int gr = row0 + r;
        if (gr < nrows) {
            g_asrc[gr * 4 + h] = sa;
            g_adst[gr * 4 + h] = da;
        }
    }
}

// ============================================================================
// scan (3 small kernels)
// ============================================================================
__global__ void k_scanA(int n) {
    __shared__ int sh[512];
    int i = blockIdx.x * 512 + threadIdx.x;
    int v = (i < n) ? g_cnt[i] : 0;
    sh[threadIdx.x] = v;
    __syncthreads();
    #pragma unroll
    for (int off = 1; off < 512; off <<= 1) {
        int t = (threadIdx.x >= off) ? sh[threadIdx.x - off] : 0;
        __syncthreads();
        sh[threadIdx.x] += t;
        __syncthreads();
    }
    if (i < n) g_rowptr[i] = sh[threadIdx.x] - v;
    if (threadIdx.x == 511) g_bsum[blockIdx.x] = sh[511];
}

__global__ void k_scanB(int nch) {
    __shared__ int sh[256];
    int v = (threadIdx.x < nch) ? g_bsum[threadIdx.x] : 0;
    sh[threadIdx.x] = v;
    __syncthreads();
    #pragma unroll
    for (int off = 1; off < 256; off <<= 1) {
        int t = (threadIdx.x >= off) ? sh[threadIdx.x - off] : 0;
        __syncthreads();
        sh[threadIdx.x] += t;
        __syncthreads();
    }
    if (threadIdx.x < nch) g_bsum[threadIdx.x] = sh[threadIdx.x] - v;
}

__global__ void k_scanC(int n, int e) {
    int i = blockIdx.x * blockDim.x + threadIdx.x;
    if (i < n) {
        int v = g_rowptr[i] + g_bsum[i >> 9];
        g_rowptr[i] = v;
        g_cursor[i] = v;
    }
    if (i == 0) g_rowptr[n] = e;
}

// ============================================================================
// K2: edge-parallel softmax weights (NO max pass; magnitudes bounded, fp32 safe)
//     w = exp(leaky(asrc[src]+adst[dst])); atomic denominator per dst.
//     Index range [e, e+n) handles the self loops.
// ============================================================================
__global__ __launch_bounds__(256) void k_edgeW(const int* __restrict__ src,
                                               const int* __restrict__ dst,
                                               int n, int e)
{
    int i = blockIdx.x * 256 + threadIdx.x;
    if (i < e) {
        int s = src[i], d = dst[i];
        float4 a = ((const float4*)g_asrc)[s];
        float4 b = ((const float4*)g_adst)[d];
        float4 w = make_float4(fexp(lrelu(a.x + b.x)), fexp(lrelu(a.y + b.y)),
                               fexp(lrelu(a.z + b.z)), fexp(lrelu(a.w + b.w)));
        ((float4*)g_w)[i] = w;
        float* dn = g_dnm + d * 4;
        atomicAdd(dn + 0, w.x);
        atomicAdd(dn + 1, w.y);
        atomicAdd(dn + 2, w.z);
        atomicAdd(dn + 3, w.w);
    } else if (i < e + n) {
        int v = i - e;
        float4 a = ((const float4*)g_asrc)[v];
        float4 b = ((const float4*)g_adst)[v];
        float4 w = make_float4(fexp(lrelu(a.x + b.x)), fexp(lrelu(a.y + b.y)),
                               fexp(lrelu(a.z + b.z)), fexp(lrelu(a.w + b.w)));
        ((float4*)g_wself)[v] = w;
        float* dn = g_dnm + v * 4;
        atomicAdd(dn + 0, w.x);
        atomicAdd(dn + 1, w.y);
        atomicAdd(dn + 2, w.z);
        atomicAdd(dn + 3, w.w);
    }
}

// ============================================================================
// K3: scatter src + weights into CSR order
// ============================================================================
__global__ void k_scatter(const int* __restrict__ src, const int* __restrict__ dst, int e) {
    for (int i = blockIdx.x * blockDim.x + threadIdx.x; i < e;
         i += gridDim.x * blockDim.x) {
        int d = dst[i];
        int pos = atomicAdd(&g_cursor[d], 1);
        g_csrc[pos] = src[i];
        ((float4*)g_wcsr)[pos] = ((const float4*)g_w)[i];
    }
}

// ============================================================================
// K4: warp-per-node weighted gather of h rows; head-mean folded; writes out.
//     Pure independent loads + FMA (no exp, no shuffles, no branches).
// ============================================================================
__global__ __launch_bounds__(256) void k_gather(float* __restrict__ out, int n)
{
    int gw = (blockIdx.x * blockDim.x + threadIdx.x) >> 5;
    if (gw >= n) return;
    const int lane = threadIdx.x & 31;

    float4 ws = ((const float4*)g_wself)[gw];
    const float2* hp = (const float2*)(g_h + (size_t)gw * 256);
    float2 v0 = hp[lane], v1 = hp[32 + lane], v2 = hp[64 + lane], v3 = hp[96 + lane];
    float2 A0 = make_float2(ws.x * v0.x, ws.x * v0.y);
    float2 A1 = make_float2(ws.y * v1.x, ws.y * v1.y);
    float2 A2 = make_float2(ws.z * v2.x, ws.z * v2.y);
    float2 A3 = make_float2(ws.w * v3.x, ws.w * v3.y);

    const int eb = g_rowptr[gw], ee = g_rowptr[gw + 1];
    #pragma unroll 2
    for (int e = eb; e < ee; e++) {
        int src  = g_csrc[e];
        float4 w = ((const float4*)g_wcsr)[e];
        const float2* sp = (const float2*)(g_h + (size_t)src * 256);
        float2 b0 = sp[lane], b1 = sp[32 + lane], b2 = sp[64 + lane], b3 = sp[96 + lane];
        A0.x = fmaf(w.x, b0.x, A0.x); A0.y = fmaf(w.x, b0.y, A0.y);
        A1.x = fmaf(w.y, b1.x, A1.x); A1.y = fmaf(w.y, b1.y, A1.y);
        A2.x = fmaf(w.z, b2.x, A2.x); A2.y = fmaf(w.z, b2.y, A2.y);
        A3.x = fmaf(w.w, b3.x, A3.x); A3.y = fmaf(w.w, b3.y, A3.y);
    }

    float4 dn = ((const float4*)g_dnm)[gw];
    float i0 = 0.25f / dn.x, i1 = 0.25f / dn.y, i2 = 0.25f / dn.z, i3 = 0.25f / dn.w;
    float2 o;
    o.x = A0.x * i0 + A1.x * i1 + A2.x * i2 + A3.x * i3;
    o.y = A0.y * i0 + A1.y * i1 + A2.y * i2 + A3.y * i3;
    ((float2*)out)[(size_t)gw * 32 + lane] = o;
}

// ============================================================================
// BatchNorm (batch stats; gat_bias cancels) + ReLU
// ============================================================================
__global__ void k_bnstats(const float* __restrict__ out, int nnodes) {
    __shared__ double shs[256], shq[256];
    const int c = threadIdx.x & 63;
    const int g = threadIdx.x >> 6;
    double s = 0.0, q = 0.0;
    for (int r = blockIdx.x * 4 + g; r < nnodes; r += gridDim.x * 4) {
        float v = out[(size_t)r * D + c];
        s += v;
        q += (double)v * v;
    }
    shs[threadIdx.x] = s; shq[threadIdx.x] = q;
    __syncthreads();
    if (g == 0) {
        s = shs[c] + shs[c + 64] + shs[c + 128] + shs[c + 192];
        q = shq[c] + shq[c + 64] + shq[c + 128] + shq[c + 192];
        atomicAdd(&g_sums[c], s);
        atomicAdd(&g_sums[64 + c], q);
    }
}

__global__ void k_bnprep(const float* __restrict__ gamma,
                         const float* __restrict__ beta, int nnodes) {
    int c = threadIdx.x;
    if (c < 64) {
        double mean = g_sums[c] / nnodes;
        double var  = g_sums[64 + c] / nnodes - mean * mean;
        float scale = gamma[c] * rsqrtf((float)var + BN_EPS);
        g_bnsc[c] = scale;
        g_bnsh[c] = beta[c] - (float)mean * scale;
    }
}

__global__ void k_bnfinal(float* __restrict__ out, int nnodes) {
    int i = blockIdx.x * blockDim.x + threadIdx.x;
    int total = nnodes * 16;
    if (i >= total) return;
    int c4 = (i & 15) << 2;
    float4 v = ((float4*)out)[i];
    float4 sc = *(const float4*)(g_bnsc + c4);
    float4 sh = *(const float4*)(g_bnsh + c4);
    v.x = fmaxf(0.f, v.x * sc.x + sh.x);
    v.y = fmaxf(0.f, v.y * sc.y + sh.y);
    v.z = fmaxf(0.f, v.z * sc.z + sh.z);
    v.w = fmaxf(0.f, v.w * sc.w + sh.w);
    ((float4*)out)[i] = v;
}

// ============================================================================
extern "C" void kernel_launch(void* const* d_in, const int* in_sizes, int n_in,
                              void* d_out, int out_size)
{
    const float* x    = (const float*)d_in[0];
    const int*   ei   = (const int*)  d_in[1];
    const float* Wlin = (const float*)d_in[2];
    const float* blin = (const float*)d_in[3];
    const float* pw   = (const float*)d_in[4];
    const float* Wgat = (const float*)d_in[5];
    const float* attS = (const float*)d_in[6];
    const float* attD = (const float*)d_in[7];
    // d_in[8] = gat_bias: cancels under batch-stat BatchNorm.
    const float* gamma = (const float*)d_in[9];
    const float* beta  = (const float*)d_in[10];
    float* out = (float*)d_out;

    int n = in_sizes[0] / D;     // 50000
    int e = in_sizes[1] / 2;     // 800000
    const int* srcA = ei;
    const int* dstA = ei + e;

    static int inited = 0;
    if (!inited) {
        cudaFuncSetAttribute(k_linear2, cudaFuncAttributeMaxDynamicSharedMemorySize, K1_SMEM);
        inited = 1;
    }

    int nch = (n + 511) / 512;

    k_prep<<<200, 256>>>(Wgat, attS, attD, n);                              // 0
    k_linear2<<<(n + 63) / 64, 256, K1_SMEM>>>(x, Wlin, blin, pw, Wgat,
                                               dstA, n, e);                 // 1
    k_scanA<<<nch, 512>>>(n);                                               // 2
    k_edgeW<<<(e + n + 255) / 256, 256>>>(srcA, dstA, n, e);                // 3 (profiled)
    k_scanB<<<1, 256>>>(nch);                                               // 4
    k_scanC<<<(n + 255) / 256, 256>>>(n, e);                                // 5
    k_scatter<<<1024, 256>>>(srcA, dstA, e);                                // 6
    k_gather<<<(n * 32 + 255) / 256, 256>>>(out, n);                        // 7
    k_bnstats<<<200, 256>>>(out, n);                                        // 8
    k_bnprep<<<1, 64>>>(gamma, beta, n);                                    // 9
    k_bnfinal<<<(n * 16 + 255) / 256, 256>>>(out, n);                       // 10
}

// round 5
// speedup vs baseline: 1.8534x; 1.2015x over previous
#include <cuda_runtime.h>
#include <cuda_fp16.h>
#include <cstdint>
#include <cstddef>

#define D   64
#define H   4
#define NEG 0.2f
#define BN_EPS 1e-5f

#define NMAX 50000
#define EMAX 800000

// ---------------- scratch (static device globals; no allocation) ----------------
__device__ __half2 g_hh[(size_t)NMAX * 128];    // [N][pair p][head h] fp16 features
__device__ float  g_asrc[NMAX * H];
__device__ float  g_adst[NMAX * H];
__device__ float  g_wcsr[(size_t)EMAX * H];     // per-edge weights (CSR order)
__device__ float  g_wself[NMAX * H];
__device__ float  g_dnm[NMAX * H];              // softmax denominators (atomic)
__device__ float  g_cs[H * D];                  // W_gat_h^T att_src_h
__device__ float  g_cd[H * D];                  // W_gat_h^T att_dst_h
__device__ int    g_cnt[NMAX];
__device__ int    g_rowptr[NMAX + 1];
__device__ int    g_cursor[NMAX];
__device__ int    g_csrc[EMAX];
__device__ int    g_bsum[256];
__device__ double g_sums[128];                  // [0:64) sum, [64:128) sumsq
__device__ float  g_bnsc[64], g_bnsh[64];

// ---------------- fast exp: FMA polynomial (no MUFU) ----------------
__device__ __forceinline__ float fexp(float x) {
    x = fmaxf(x, -80.f);
    float y  = x * 1.44269504089f;
    float t  = y + 12582912.0f;
    int   ki = __float_as_int(t) - 0x4B400000;
    float r  = y - (t - 12582912.0f);
    float p  = 1.5403530e-4f;
    p = fmaf(p, r, 1.3333558e-3f);
    p = fmaf(p, r, 9.6181291e-3f);
    p = fmaf(p, r, 5.5504109e-2f);
    p = fmaf(p, r, 2.4022651e-1f);
    p = fmaf(p, r, 6.9314718e-1f);
    p = fmaf(p, r, 1.0f);
    return __int_as_float(__float_as_int(p) + (ki << 23));
}

__device__ __forceinline__ float lrelu(float v) { return (v >= 0.f) ? v : NEG * v; }

// ============================================================================
// prep kernels (3 tiny launches so launch #4 = k_linear2 gets profiled)
// ============================================================================
__global__ void k_prep_vec(const float* __restrict__ Wgat,
                           const float* __restrict__ attS,
                           const float* __restrict__ attD) {
    int tid = threadIdx.x;              // 256
    int h = tid >> 6, k = tid & 63;
    float s = 0.f, d2 = 0.f;
    #pragma unroll 8
    for (int dd = 0; dd < 64; dd++) {
        float wv = Wgat[(h * 64 + dd) * 64 + k];
        s  += attS[h * 64 + dd] * wv;
        d2 += attD[h * 64 + dd] * wv;
    }
    g_cs[tid] = s;
    g_cd[tid] = d2;
}

__global__ void k_zero(int n) {
    int gid = blockIdx.x * blockDim.x + threadIdx.x;
    int stride = gridDim.x * blockDim.x;
    for (int i = gid; i < n; i += stride) g_cnt[i] = 0;
    for (int i = gid; i < n * 4; i += stride) g_dnm[i] = 0.f;
}

__global__ void k_zero_sums() {
    if (threadIdx.x < 128) g_sums[threadIdx.x] = 0.0;
}

// ============================================================================
// K1: fused  u = PReLU(x W_lin^T + b);  h = u W_gat^T (fp16, head-interleaved);
//     a_src/a_dst dots;  + destination histogram (overlapped)
// ============================================================================
#define K1_SMEM ((2*64*72 + 64*264 + 2*4*68) * 4)

__global__ __launch_bounds__(256) void k_linear2(
    const float* __restrict__ x, const float* __restrict__ Wlin,
    const float* __restrict__ blin, const float* __restrict__ pw,
    const float* __restrict__ Wgat, const int* __restrict__ dstA,
    int nrows, int nedges)
{
    extern __shared__ float sm[];
    float* sX  = sm;                     // [64][72]
    float* sU  = sm + 64 * 72;           // [64][72]
    float* sW  = sm + 2 * 64 * 72;       // [64][264]
    float* sC  = sm + 2 * 64 * 72 + 64 * 264;   // [4][68]
    float* sC2 = sC + 4 * 68;                   // [4][68]
    const int tid  = threadIdx.x;
    const int row0 = blockIdx.x * 64;

    // destination histogram (independent, overlaps FFMA work)
    {
        int gid = blockIdx.x * 256 + tid;
        int stride = gridDim.x * 256;
        for (int i = gid; i < nedges; i += stride)
            atomicAdd(&g_cnt[dstA[i]], 1);
    }

    {
        int h = tid >> 6, k = tid & 63;
        sC [h * 68 + k] = g_cs[tid];
        sC2[h * 68 + k] = g_cd[tid];
    }
    for (int i = tid; i < 64 * 64; i += 256) {
        int r = i >> 6, k = i & 63;
        int gr = row0 + r;
        sX[k * 72 + r] = (gr < nrows) ? x[(size_t)gr * D + k] : 0.f;
    }
    for (int i = tid; i < 64 * 64; i += 256) {
        int j = i >> 6, k = i & 63;
        sW[k * 264 + j] = Wlin[i];
    }
    __syncthreads();

    // ---- stage A: u = PReLU(x W_lin^T + b) -> sU (transposed) ----
    {
        const int rg = (tid >> 4) << 2;
        const int cg = (tid & 15) << 2;
        float acc[4][4];
        #pragma unroll
        for (int a = 0; a < 4; a++)
            #pragma unroll
            for (int b = 0; b < 4; b++) acc[a][b] = 0.f;
        #pragma unroll 8
        for (int k = 0; k < 64; k++) {
            float4 a4 = *(const float4*)(sX + k * 72 + rg);
            float4 b4 = *(const float4*)(sW + k * 264 + cg);
            float av[4] = {a4.x, a4.y, a4.z, a4.w};
            float bv[4] = {b4.x, b4.y, b4.z, b4.w};
            #pragma unroll
            for (int ri = 0; ri < 4; ri++)
                #pragma unroll
                for (int cj = 0; cj < 4; cj++) acc[ri][cj] += av[ri] * bv[cj];
        }
        float4 bb = *(const float4*)(blin + cg);
        float4 pp = *(const float4*)(pw + cg);
        float bvb[4] = {bb.x, bb.y, bb.z, bb.w};
        float pvb[4] = {pp.x, pp.y, pp.z, pp.w};
        #pragma unroll
        for (int ri = 0; ri < 4; ri++)
            #pragma unroll
            for (int cj = 0; cj < 4; cj++) {
                float v = acc[ri][cj] + bvb[cj];
                v = (v >= 0.f) ? v : pvb[cj] * v;
                sU[(cg + cj) * 72 + rg + ri] = v;
            }
    }
    __syncthreads();
    for (int i = tid; i < 256 * 64; i += 256) {
        int m = i >> 6, k = i & 63;
        sW[k * 264 + m] = Wgat[i];
    }
    __syncthreads();

    // ---- stage B: h = u W_gat^T (8x8 micro-tiles) ----
    const int lane = tid & 31;
    const int r0   = (tid >> 5) << 3;
    const int mlo  = lane << 2;          // cols [mlo,mlo+4) heads 0/1
    const int mhi  = 128 + mlo;          // heads 2/3
    float acc[8][8];
    #pragma unroll
    for (int a = 0; a < 8; a++)
        #pragma unroll
        for (int b = 0; b < 8; b++) acc[a][b] = 0.f;

    #pragma unroll 8
    for (int k = 0; k < 64; k++) {
        float4 a0 = *(const float4*)(sU + k * 72 + r0);
        float4 a1 = *(const float4*)(sU + k * 72 + r0 + 4);
        float4 b0 = *(const float4*)(sW + k * 264 + mlo);
        float4 b1 = *(const float4*)(sW + k * 264 + mhi);
        float av[8] = {a0.x, a0.y, a0.z, a0.w, a1.x, a1.y, a1.z, a1.w};
        float bv[8] = {b0.x, b0.y, b0.z, b0.w, b1.x, b1.y, b1.z, b1.w};
        #pragma unroll
        for (int ri = 0; ri < 8; ri++)
            #pragma unroll
            for (int cj = 0; cj < 8; cj++) acc[ri][cj] += av[ri] * bv[cj];
    }

    // fp16 head-interleaved store: g_hh[gr*128 + p*4 + h] = half2(col 2p, col 2p+1)
    const int hA = mlo >> 6;          // 0 or 1
    const int hB = hA + 2;            // 2 or 3
    const int p0 = (mlo & 63) >> 1;   // even pair index
    #pragma unroll
    for (int ri = 0; ri < 8; ri++) {
        int gr = row0 + r0 + ri;
        if (gr < nrows) {
            __half2* hp = g_hh + (size_t)gr * 128;
            hp[p0 * 4 + hA]       = __floats2half2_rn(acc[ri][0], acc[ri][1]);
            hp[(p0 + 1) * 4 + hA] = __floats2half2_rn(acc[ri][2], acc[ri][3]);
            hp[p0 * 4 + hB]       = __floats2half2_rn(acc[ri][4], acc[ri][5]);
            hp[(p0 + 1) * 4 + hB] = __floats2half2_rn(acc[ri][6], acc[ri][7]);
        }
    }

    // attention dots from sU
    {
        const int r = tid >> 2, h = tid & 3;
        float sa = 0.f, da = 0.f;
        #pragma unroll 8
        for (int k = 0; k < 64; k++) {
            float uv = sU[k * 72 + r];
            sa += uv * sC [h * 68 + k];
            da += uv * sC2[h * 68 + k];
        }
        int gr = row0 + r;
        if (gr < nrows) {
            g_asrc[gr * 4 + h] = sa;
            g_adst[gr * 4 + h] = da;
        }
    }
}

// ============================================================================
// scan
// ============================================================================
__global__ void k_scanA(int n) {
    __shared__ int sh[512];
    int i = blockIdx.x * 512 + threadIdx.x;
    int v = (i < n) ? g_cnt[i] : 0;
    sh[threadIdx.x] = v;
    __syncthreads();
    #pragma unroll
    for (int off = 1; off < 512; off <<= 1) {
        int t = (threadIdx.x >= off) ? sh[threadIdx.x - off] : 0;
        __syncthreads();
        sh[threadIdx.x] += t;
        __syncthreads();
    }
    if (i < n) g_rowptr[i] = sh[threadIdx.x] - v;
    if (threadIdx.x == 511) g_bsum[blockIdx.x] = sh[511];
}

__global__ void k_scanB(int nch) {
    __shared__ int sh[256];
    int v = (threadIdx.x < nch) ? g_bsum[threadIdx.x] : 0;
    sh[threadIdx.x] = v;
    __syncthreads();
    #pragma unroll
    for (int off = 1; off < 256; off <<= 1) {
        int t = (threadIdx.x >= off) ? sh[threadIdx.x - off] : 0;
        __syncthreads();
        sh[threadIdx.x] += t;
        __syncthreads();
    }
    if (threadIdx.x < nch) g_bsum[threadIdx.x] = sh[threadIdx.x] - v;
}

__global__ void k_scanC(int n, int e) {
    int i = blockIdx.x * blockDim.x + threadIdx.x;
    if (i < n) {
        int v = g_rowptr[i] + g_bsum[i >> 9];
        g_rowptr[i] = v;
        g_cursor[i] = v;
    }
    if (i == 0) g_rowptr[n] = e;
}

// ============================================================================
// K2: fused edge weights + CSR scatter (no max pass; magnitudes bounded).
//     w = exp(leaky(asrc[src]+adst[dst])), written straight into CSR slot;
//     fp32 atomic denominator per dst. Range [e, e+n) = self loops.
// ============================================================================
__global__ __launch_bounds__(256) void k_edgeW(const int* __restrict__ src,
                                               const int* __restrict__ dst,
                                               int n, int e)
{
    int i = blockIdx.x * 256 + threadIdx.x;
    if (i < e) {
        int s = src[i], d = dst[i];
        float4 a = ((const float4*)g_asrc)[s];
        float4 b = ((const float4*)g_adst)[d];
        float4 w = make_float4(fexp(lrelu(a.x + b.x)), fexp(lrelu(a.y + b.y)),
                               fexp(lrelu(a.z + b.z)), fexp(lrelu(a.w + b.w)));
        int pos = atomicAdd(&g_cursor[d], 1);
        g_csrc[pos] = s;
        ((float4*)g_wcsr)[pos] = w;
        float* dn = g_dnm + d * 4;
        atomicAdd(dn + 0, w.x);
        atomicAdd(dn + 1, w.y);
        atomicAdd(dn + 2, w.z);
        atomicAdd(dn + 3, w.w);
    } else if (i < e + n) {
        int v = i - e;
        float4 a = ((const float4*)g_asrc)[v];
        float4 b = ((const float4*)g_adst)[v];
        float4 w = make_float4(fexp(lrelu(a.x + b.x)), fexp(lrelu(a.y + b.y)),
                               fexp(lrelu(a.z + b.z)), fexp(lrelu(a.w + b.w)));
        ((float4*)g_wself)[v] = w;
        float* dn = g_dnm + v * 4;
        atomicAdd(dn + 0, w.x);
        atomicAdd(dn + 1, w.y);
        atomicAdd(dn + 2, w.z);
        atomicAdd(dn + 3, w.w);
    }
}

// ============================================================================
// K4: warp-per-node weighted gather. One LDG.128 per lane per source row
//     (head-interleaved fp16). Head-mean folded; writes pre-BN out.
// ============================================================================
__global__ __launch_bounds__(256) void k_gather(float* __restrict__ out, int n)
{
    int gw = (blockIdx.x * blockDim.x + threadIdx.x) >> 5;
    if (gw >= n) return;
    const int lane = threadIdx.x & 31;

    float4 ws = ((const float4*)g_wself)[gw];
    uint4 hv = ((const uint4*)(g_hh + (size_t)gw * 128))[lane];
    float2 f0 = __half22float2(*(__half2*)&hv.x);
    float2 f1 = __half22float2(*(__half2*)&hv.y);
    float2 f2 = __half22float2(*(__half2*)&hv.z);
    float2 f3 = __half22float2(*(__half2*)&hv.w);
    float2 A0 = make_float2(ws.x * f0.x, ws.x * f0.y);
    float2 A1 = make_float2(ws.y * f1.x, ws.y * f1.y);
    float2 A2 = make_float2(ws.z * f2.x, ws.z * f2.y);
    float2 A3 = make_float2(ws.w * f3.x, ws.w * f3.y);

    const int eb = g_rowptr[gw], ee = g_rowptr[gw + 1];
    #pragma unroll 2
    for (int e = eb; e < ee; e++) {
        int src  = g_csrc[e];
        float4 w = ((const float4*)g_wcsr)[e];
        uint4 sv = ((const uint4*)(g_hh + (size_t)src * 128))[lane];
        float2 b0 = __half22float2(*(__half2*)&sv.x);
        float2 b1 = __half22float2(*(__half2*)&sv.y);
        float2 b2 = __half22float2(*(__half2*)&sv.z);
        float2 b3 = __half22float2(*(__half2*)&sv.w);
        A0.x = fmaf(w.x, b0.x, A0.x); A0.y = fmaf(w.x, b0.y, A0.y);
        A1.x = fmaf(w.y, b1.x, A1.x); A1.y = fmaf(w.y, b1.y, A1.y);
        A2.x = fmaf(w.z, b2.x, A2.x); A2.y = fmaf(w.z, b2.y, A2.y);
        A3.x = fmaf(w.w, b3.x, A3.x); A3.y = fmaf(w.w, b3.y, A3.y);
    }

    float4 dn = ((const float4*)g_dnm)[gw];
    float i0 = 0.25f / dn.x, i1 = 0.25f / dn.y, i2 = 0.25f / dn.z, i3 = 0.25f / dn.w;
    float2 o;
    o.x = A0.x * i0 + A1.x * i1 + A2.x * i2 + A3.x * i3;
    o.y = A0.y * i0 + A1.y * i1 + A2.y * i2 + A3.y * i3;
    ((float2*)out)[(size_t)gw * 32 + lane] = o;   // cols (2*lane, 2*lane+1)
}

// ============================================================================
// BatchNorm (batch stats; gat_bias cancels) + ReLU
// ============================================================================
__global__ void k_bnstats(const float* __restrict__ out, int nnodes) {
    __shared__ double shs[256], shq[256];
    const int c = threadIdx.x & 63;
    const int g = threadIdx.x >> 6;
    double s = 0.0, q = 0.0;
    for (int r = blockIdx.x * 4 + g; r < nnodes; r += gridDim.x * 4) {
        float v = out[(size_t)r * D + c];
        s += v;
        q += (double)v * v;
    }
    shs[threadIdx.x] = s; shq[threadIdx.x] = q;
    __syncthreads();
    if (g == 0) {
        s = shs[c] + shs[c + 64] + shs[c + 128] + shs[c + 192];
        q = shq[c] + shq[c + 64] + shq[c + 128] + shq[c + 192];
        atomicAdd(&g_sums[c], s);
        atomicAdd(&g_sums[64 + c], q);
    }
}

__global__ void k_bnprep(const float* __restrict__ gamma,
                         const float* __restrict__ beta, int nnodes) {
    int c = threadIdx.x;
    if (c < 64) {
        double mean = g_sums[c] / nnodes;
        double var  = g_sums[64 + c] / nnodes - mean * mean;
        float scale = gamma[c] * rsqrtf((float)var + BN_EPS);
        g_bnsc[c] = scale;
        g_bnsh[c] = beta[c] - (float)mean * scale;
    }
}

__global__ void k_bnfinal(float* __restrict__ out, int nnodes) {
    int i = blockIdx.x * blockDim.x + threadIdx.x;
    int total = nnodes * 16;
    if (i >= total) return;
    int c4 = (i & 15) << 2;
    float4 v = ((float4*)out)[i];
    float4 sc = *(const float4*)(g_bnsc + c4);
    float4 sh = *(const float4*)(g_bnsh + c4);
    v.x = fmaxf(0.f, v.x * sc.x + sh.x);
    v.y = fmaxf(0.f, v.y * sc.y + sh.y);
    v.z = fmaxf(0.f, v.z * sc.z + sh.z);
    v.w = fmaxf(0.f, v.w * sc.w + sh.w);
    ((float4*)out)[i] = v;
}

// ============================================================================
extern "C" void kernel_launch(void* const* d_in, const int* in_sizes, int n_in,
                              void* d_out, int out_size)
{
    const float* x    = (const float*)d_in[0];
    const int*   ei   = (const int*)  d_in[1];
    const float* Wlin = (const float*)d_in[2];
    const float* blin = (const float*)d_in[3];
    const float* pw   = (const float*)d_in[4];
    const float* Wgat = (const float*)d_in[5];
    const float* attS = (const float*)d_in[6];
    const float* attD = (const float*)d_in[7];
    // d_in[8] = gat_bias: cancels under batch-stat BatchNorm.
    const float* gamma = (const float*)d_in[9];
    const float* beta  = (const float*)d_in[10];
    float* out = (float*)d_out;

    int n = in_sizes[0] / D;     // 50000
    int e = in_sizes[1] / 2;     // 800000
    const int* srcA = ei;
    const int* dstA = ei + e;

    static int inited = 0;
    if (!inited) {
        cudaFuncSetAttribute(k_linear2, cudaFuncAttributeMaxDynamicSharedMemorySize, K1_SMEM);
        inited = 1;
    }

    int nch = (n + 511) / 512;

    k_prep_vec<<<1, 256>>>(Wgat, attS, attD);                                // 0
    k_zero<<<200, 256>>>(n);                                                 // 1
    k_zero_sums<<<1, 128>>>();                                               // 2
    k_linear2<<<(n + 63) / 64, 256, K1_SMEM>>>(x, Wlin, blin, pw, Wgat,
                                               dstA, n, e);                  // 3 (profiled)
    k_scanA<<<nch, 512>>>(n);                                                // 4
    k_scanB<<<1, 256>>>(nch);                                                // 5
    k_scanC<<<(n + 255) / 256, 256>>>(n, e);                                 // 6
    k_edgeW<<<(e + n + 255) / 256, 256>>>(srcA, dstA, n, e);                 // 7
    k_gather<<<(n * 32 + 255) / 256, 256>>>(out, n);                         // 8
    k_bnstats<<<200, 256>>>(out, n);                                         // 9
    k_bnprep<<<1, 64>>>(gamma, beta, n);                                     // 10
    k_bnfinal<<<(n * 16 + 255) / 256, 256>>>(out, n);                        // 11
}